// round 5
// baseline (speedup 1.0000x reference)
#include <cuda_runtime.h>
#include <cstdint>

#define BATCH 4
#define SEQ   2048
#define DMODEL 512
#define NHEAD 8
#define DHEAD 64
#define NKT  (SEQ / 64)  // 32 k-tiles

// Scratch (allocation-free rule: __device__ globals)
__device__ float g_q[(size_t)BATCH * SEQ * DMODEL];
__device__ float g_k[(size_t)BATCH * SEQ * DMODEL];
__device__ float g_v[(size_t)BATCH * SEQ * DMODEL];
__device__ float g_a[(size_t)BATCH * SEQ * DMODEL];

__device__ __forceinline__ float to_tf32(float x) {
    asm("cvt.rna.tf32.f32 %0, %0;" : "+f"(x));
    return x;
}
__device__ __forceinline__ unsigned f2u(float x) { return __float_as_uint(x); }
__device__ __forceinline__ unsigned s2u(const void* p) {
    return (unsigned)__cvta_generic_to_shared(p);
}

__device__ __forceinline__ void mma_tf32(float c[4], const unsigned a[4],
                                         unsigned b0, unsigned b1)
{
    asm volatile(
        "mma.sync.aligned.m16n8k8.row.col.f32.tf32.tf32.f32 "
        "{%0,%1,%2,%3}, {%4,%5,%6,%7}, {%8,%9}, {%0,%1,%2,%3};\n"
        : "+f"(c[0]), "+f"(c[1]), "+f"(c[2]), "+f"(c[3])
        : "r"(a[0]), "r"(a[1]), "r"(a[2]), "r"(a[3]), "r"(b0), "r"(b1));
}

__device__ __forceinline__ void ldsm4(unsigned r[4], unsigned addr) {
    asm volatile("ldmatrix.sync.aligned.m8n8.x4.shared.b16 {%0,%1,%2,%3}, [%4];"
        : "=r"(r[0]), "=r"(r[1]), "=r"(r[2]), "=r"(r[3]) : "r"(addr));
}

#define CP16(dst, src) \
    asm volatile("cp.async.cg.shared.global [%0], [%1], 16;" :: "r"(dst), "l"(src))
#define CP_COMMIT()  asm volatile("cp.async.commit_group;")
#define CP_WAIT0()   asm volatile("cp.async.wait_group 0;" ::: "memory")

// ----------------------------------------------------------------------------
// tf32 GEMM + bias (unchanged).
// MODE: 0 = plain fp32 out; 1 = tf32-rounded out; 2 = tf32-rounded * 0.125
// ----------------------------------------------------------------------------
template<int MODE>
__global__ void __launch_bounds__(256) gemm2(
    const float* __restrict__ A, const float* __restrict__ W,
    const float* __restrict__ bias, float* __restrict__ C)
{
    __shared__ float As[2][128 * 20];
    __shared__ float Wt[2][64 * 20];

    const int tid = threadIdx.x;
    const int lane = tid & 31, warp = tid >> 5;
    const int mw = (warp >> 1) * 32;
    const int nw = (warp & 1) * 32;
    const int r = lane >> 2, c = lane & 3;

    float acc[2][4][4];
#pragma unroll
    for (int i = 0; i < 2; i++)
#pragma unroll
        for (int j = 0; j < 4; j++)
#pragma unroll
            for (int k = 0; k < 4; k++) acc[i][j][k] = 0.f;

    const float* Ab = A + (size_t)blockIdx.y * 128 * 512;
    const float* Wb = W + blockIdx.x * 64;

    const int arow = tid >> 2, ac4 = tid & 3;
    const int wrow = tid >> 4, wc4 = tid & 15;

    unsigned uA0 = s2u(&As[0][0]) +
        (((mw + (lane & 15)) * 20) + ((lane >> 4) << 2)) * 4;
    unsigned uA1 = uA0 + 16 * 20 * 4;
    unsigned uB0 = s2u(&Wt[0][0]) +
        (((nw + (lane & 7) + ((lane >> 4) << 3)) * 20) + (((lane >> 3) & 1) << 2)) * 4;
    unsigned uB1 = uB0 + 16 * 20 * 4;

    float4 aR0, aR1, wR;
    aR0 = *(const float4*)(Ab + (size_t)arow * 512 + ac4 * 4);
    aR1 = *(const float4*)(Ab + (size_t)(arow + 64) * 512 + ac4 * 4);
    wR  = *(const float4*)(Wb + (size_t)wrow * 512 + wc4 * 4);
    {
        float4 v = aR0;
        v.x = to_tf32(v.x); v.y = to_tf32(v.y); v.z = to_tf32(v.z); v.w = to_tf32(v.w);
        *(float4*)&As[0][arow * 20 + ac4 * 4] = v;
        v = aR1;
        v.x = to_tf32(v.x); v.y = to_tf32(v.y); v.z = to_tf32(v.z); v.w = to_tf32(v.w);
        *(float4*)&As[0][(arow + 64) * 20 + ac4 * 4] = v;
        Wt[0][(wc4 * 4 + 0) * 20 + wrow] = to_tf32(wR.x);
        Wt[0][(wc4 * 4 + 1) * 20 + wrow] = to_tf32(wR.y);
        Wt[0][(wc4 * 4 + 2) * 20 + wrow] = to_tf32(wR.z);
        Wt[0][(wc4 * 4 + 3) * 20 + wrow] = to_tf32(wR.w);
    }
    __syncthreads();

    for (int k0 = 0; k0 < 512; k0 += 16) {
        const int cur = (k0 >> 4) & 1;
        const bool nxt = (k0 + 16) < 512;
        if (nxt) {
            aR0 = *(const float4*)(Ab + (size_t)arow * 512 + k0 + 16 + ac4 * 4);
            aR1 = *(const float4*)(Ab + (size_t)(arow + 64) * 512 + k0 + 16 + ac4 * 4);
            wR  = *(const float4*)(Wb + (size_t)(k0 + 16 + wrow) * 512 + wc4 * 4);
        }
#pragma unroll
        for (int ks = 0; ks < 16; ks += 8) {
            unsigned a0[4], a1[4], bF[4];
            ldsm4(a0, uA0 + cur * 10240 + ks * 4);
            ldsm4(a1, uA1 + cur * 10240 + ks * 4);
            ldsm4(bF, uB0 + cur * 5120 + ks * 4);
            mma_tf32(acc[0][0], a0, bF[0], bF[1]);
            mma_tf32(acc[0][1], a0, bF[2], bF[3]);
            mma_tf32(acc[1][0], a1, bF[0], bF[1]);
            mma_tf32(acc[1][1], a1, bF[2], bF[3]);
            ldsm4(bF, uB1 + cur * 5120 + ks * 4);
            mma_tf32(acc[0][2], a0, bF[0], bF[1]);
            mma_tf32(acc[0][3], a0, bF[2], bF[3]);
            mma_tf32(acc[1][2], a1, bF[0], bF[1]);
            mma_tf32(acc[1][3], a1, bF[2], bF[3]);
        }
        if (nxt) {
            const int nb = cur ^ 1;
            float4 v = aR0;
            v.x = to_tf32(v.x); v.y = to_tf32(v.y); v.z = to_tf32(v.z); v.w = to_tf32(v.w);
            *(float4*)&As[nb][arow * 20 + ac4 * 4] = v;
            v = aR1;
            v.x = to_tf32(v.x); v.y = to_tf32(v.y); v.z = to_tf32(v.z); v.w = to_tf32(v.w);
            *(float4*)&As[nb][(arow + 64) * 20 + ac4 * 4] = v;
            Wt[nb][(wc4 * 4 + 0) * 20 + wrow] = to_tf32(wR.x);
            Wt[nb][(wc4 * 4 + 1) * 20 + wrow] = to_tf32(wR.y);
            Wt[nb][(wc4 * 4 + 2) * 20 + wrow] = to_tf32(wR.z);
            Wt[nb][(wc4 * 4 + 3) * 20 + wrow] = to_tf32(wR.w);
        }
        __syncthreads();
    }

#pragma unroll
    for (int mt = 0; mt < 2; mt++)
#pragma unroll
    for (int nt = 0; nt < 4; nt++) {
        int col = blockIdx.x * 64 + nw + nt * 8 + 2 * c;
        float bx = __ldg(bias + col), by = __ldg(bias + col + 1);
        size_t row0 = blockIdx.y * 128 + mw + mt * 16 + r;
        float v0 = acc[mt][nt][0] + bx, v1 = acc[mt][nt][1] + by;
        float v2 = acc[mt][nt][2] + bx, v3 = acc[mt][nt][3] + by;
        if (MODE == 2) { v0 *= 0.125f; v1 *= 0.125f; v2 *= 0.125f; v3 *= 0.125f; }
        if (MODE >= 1) {
            v0 = to_tf32(v0); v1 = to_tf32(v1); v2 = to_tf32(v2); v3 = to_tf32(v3);
        }
        *(float2*)(C + row0 * 512 + col) = make_float2(v0, v1);
        *(float2*)(C + (row0 + 8) * 512 + col) = make_float2(v2, v3);
    }
}

// ----------------------------------------------------------------------------
// Flash attention v5: no-max softmax, e spilled through weights buffer.
// Pass A: QK -> e=exp(s+mask') -> write e (canonical, own positions), sum l.
// Pass B: read own e, scale by 1/l in place, PV (no QK recompute, no K smem).
// 8 warps: 4 m16-groups x 2 key-halves. 1 barrier per k-tile.
// ----------------------------------------------------------------------------
#define QSTR 68
#define VSTR 72
#define OFF_K   4352
#define OFF_V   13056
#define OFF_MSK 22272
#define OFF_ST  24320
#define ATTN_SMEM_FLOATS 24576
#define KBUF_BYTES (4352 * 4)

__global__ void __launch_bounds__(256, 2) attn5(
    const float* __restrict__ mask, float* __restrict__ wts)
{
    extern __shared__ float sh[];
    float* msk = sh + OFF_MSK;
    float* statsf = sh + OFF_ST;   // [row][nwi] partial row-sums

    const int tid = threadIdx.x;
    const int lane = tid & 31, warp = tid >> 5;
    const int mw = (warp >> 1) * 16;
    const int nwi = warp & 1;
    const int nw = nwi * 32;
    const int r = lane >> 2, c = lane & 3;

    const int qt = blockIdx.x, bh = blockIdx.y;
    const int b = bh >> 3, h = bh & 7;
    const int q0 = qt * 64;

    const float* qg = g_q + ((size_t)(b * SEQ + q0)) * DMODEL + h * DHEAD;
    const float* kg = g_k + (size_t)b * SEQ * DMODEL + h * DHEAD;
    const float* vg = g_v + (size_t)b * SEQ * DMODEL + h * DHEAD;
    float* wb = wts + ((size_t)bh * SEQ + q0) * SEQ;

    const unsigned uQst = s2u(sh);
    const unsigned uKst = s2u(sh + OFF_K);
    const unsigned uVst = s2u(sh + OFF_V);

    // prologue: Q + K0
#pragma unroll
    for (int i = 0; i < 4; i++) {
        int f = tid + 256 * i;
        int row = f >> 4, c4 = f & 15;
        CP16(uQst + (unsigned)(row * QSTR + c4 * 4) * 4,
             qg + (size_t)row * DMODEL + c4 * 4);
        CP16(uKst + (unsigned)(row * QSTR + c4 * 4) * 4,
             kg + (size_t)row * DMODEL + c4 * 4);
    }
    CP_COMMIT();
#pragma unroll
    for (int j = 0; j < 2; j++) {
        int idx = tid + 256 * j;
        float4 mv = *(const float4*)(mask + (size_t)b * SEQ + idx * 4);
        msk[idx * 4 + 0] = mv.x * -1e9f;
        msk[idx * 4 + 1] = mv.y * -1e9f;
        msk[idx * 4 + 2] = mv.z * -1e9f;
        msk[idx * 4 + 3] = mv.w * -1e9f;
    }
    CP_WAIT0();
    __syncthreads();

    // fragment base addresses
    const unsigned uQ = uQst +
        (((mw + (lane & 15)) * QSTR) + ((lane >> 4) << 2)) * 4;
    unsigned uK[2];
#pragma unroll
    for (int ntp = 0; ntp < 2; ntp++)
        uK[ntp] = uKst +
            (((nw + ntp * 16 + (lane & 7) + ((lane >> 4) << 3)) * QSTR) +
             (((lane >> 3) & 1) << 2)) * 4;

    float l0 = 0.f, l1 = 0.f;    // register row-sums (rows mw+r, mw+r+8)

    // ======================= Pass A: QK -> e -> sum =======================
#pragma unroll 1
    for (int kt = 0; kt < NKT; ++kt) {
        const int cur = kt & 1;
        if (kt + 1 < NKT) {
            const int nb = (kt + 1) & 1;
            const float* src = kg + (size_t)(kt + 1) * 64 * DMODEL;
#pragma unroll
            for (int i = 0; i < 4; i++) {
                int f = tid + 256 * i;
                int row = f >> 4, c4 = f & 15;
                CP16(uKst + nb * KBUF_BYTES + (unsigned)(row * QSTR + c4 * 4) * 4,
                     src + (size_t)row * DMODEL + c4 * 4);
            }
            CP_COMMIT();
        }

        float sf[4][4];
#pragma unroll
        for (int nt = 0; nt < 4; nt++)
#pragma unroll
            for (int j = 0; j < 4; j++) sf[nt][j] = 0.f;

#pragma unroll
        for (int ks = 0; ks < 64; ks += 8) {
            unsigned a[4], bF[4];
            ldsm4(a, uQ + ks * 4);
            ldsm4(bF, uK[0] + cur * KBUF_BYTES + ks * 4);
            mma_tf32(sf[0], a, bF[0], bF[1]);
            mma_tf32(sf[1], a, bF[2], bF[3]);
            ldsm4(bF, uK[1] + cur * KBUF_BYTES + ks * 4);
            mma_tf32(sf[2], a, bF[0], bF[1]);
            mma_tf32(sf[3], a, bF[2], bF[3]);
        }

        float s0 = 0.f, s1 = 0.f;
#pragma unroll
        for (int nt = 0; nt < 4; nt++) {
            int col = nw + nt * 8 + 2 * c;
            float mk0 = msk[kt * 64 + col], mk1 = msk[kt * 64 + col + 1];
            float e0 = __expf(sf[nt][0] + mk0);
            float e1 = __expf(sf[nt][1] + mk1);
            float e2 = __expf(sf[nt][2] + mk0);
            float e3 = __expf(sf[nt][3] + mk1);
            float* wp = wb + (size_t)(mw + r) * SEQ + kt * 64 + col;
            *(float2*)wp = make_float2(e0, e1);              // unnormalized e
            *(float2*)(wp + 8 * SEQ) = make_float2(e2, e3);
            s0 += e0 + e1;
            s1 += e2 + e3;
        }
        s0 += __shfl_xor_sync(0xffffffffu, s0, 1);
        s0 += __shfl_xor_sync(0xffffffffu, s0, 2);
        s1 += __shfl_xor_sync(0xffffffffu, s1, 1);
        s1 += __shfl_xor_sync(0xffffffffu, s1, 2);
        l0 += s0;
        l1 += s1;

        CP_WAIT0();
        __syncthreads();
    }

    // combine warp-pair sums (once)
    if (c == 0) {
        statsf[(mw + r) * 2 + nwi] = l0;
        statsf[(mw + r + 8) * 2 + nwi] = l1;
    }

    // pass-B prologue: V0
#pragma unroll
    for (int i = 0; i < 4; i++) {
        int f = tid + 256 * i;
        int row = f >> 4, c4 = f & 15;
        CP16(uVst + (unsigned)(row * VSTR + c4 * 4) * 4,
             vg + (size_t)row * DMODEL + c4 * 4);
    }
    CP_COMMIT();
    __syncthreads();

    const float il0 = 1.f / (statsf[(mw + r) * 2] + statsf[(mw + r) * 2 + 1]);
    const float il1 = 1.f / (statsf[(mw + r + 8) * 2] + statsf[(mw + r + 8) * 2 + 1]);
    CP_WAIT0();
    __syncthreads();

    // ======================= Pass B: normalize + PV =======================
    float of[8][4];
#pragma unroll
    for (int nt8 = 0; nt8 < 8; nt8++)
#pragma unroll
        for (int j = 0; j < 4; j++) of[nt8][j] = 0.f;

#pragma unroll 1
    for (int kt = 0; kt < NKT; ++kt) {
        const int cur = kt & 1;
        if (kt + 1 < NKT) {
            const int nb = (kt + 1) & 1;
            const float* vsrc = vg + (size_t)(kt + 1) * 64 * DMODEL;
#pragma unroll
            for (int i = 0; i < 4; i++) {
                int f = tid + 256 * i;
                int row = f >> 4, c4 = f & 15;
                CP16(uVst + nb * (VSTR * 64 * 4) + (unsigned)(row * VSTR + c4 * 4) * 4,
                     vsrc + (size_t)row * DMODEL + c4 * 4);
            }
            CP_COMMIT();
        }

        // read own e values, normalize in place, keep tf32 p
        float sf[4][4];
#pragma unroll
        for (int nt = 0; nt < 4; nt++) {
            int col = nw + nt * 8 + 2 * c;
            float* wp = wb + (size_t)(mw + r) * SEQ + kt * 64 + col;
            float2 e0 = *(float2*)wp;
            float2 e1 = *(float2*)(wp + 8 * SEQ);
            float p0 = e0.x * il0, p1 = e0.y * il0;
            float p2 = e1.x * il1, p3 = e1.y * il1;
            *(float2*)wp = make_float2(p0, p1);              // final weights
            *(float2*)(wp + 8 * SEQ) = make_float2(p2, p3);
            sf[nt][0] = to_tf32(p0); sf[nt][1] = to_tf32(p1);
            sf[nt][2] = to_tf32(p2); sf[nt][3] = to_tf32(p3);
        }

        // PV over this warp's 32 keys, all 64 dims; A-frags via quad shfl
        const float* Vcur = sh + OFF_V + cur * (VSTR * 64);
        const int src0 = (lane & ~3) | (c >> 1);
        const int src1 = src0 + 2;
#pragma unroll
        for (int kb = 0; kb < 4; kb++) {
            unsigned a[4];
            {
                float g0 = __shfl_sync(0xffffffffu, sf[kb][0], src0);
                float g1 = __shfl_sync(0xffffffffu, sf[kb][1], src0);
                a[0] = f2u((c & 1) ? g1 : g0);
                float g2 = __shfl_sync(0xffffffffu, sf[kb][2], src0);
                float g3 = __shfl_sync(0xffffffffu, sf[kb][3], src0);
                a[1] = f2u((c & 1) ? g3 : g2);
                float h0 = __shfl_sync(0xffffffffu, sf[kb][0], src1);
                float h1 = __shfl_sync(0xffffffffu, sf[kb][1], src1);
                a[2] = f2u((c & 1) ? h1 : h0);
                float h2 = __shfl_sync(0xffffffffu, sf[kb][2], src1);
                float h3 = __shfl_sync(0xffffffffu, sf[kb][3], src1);
                a[3] = f2u((c & 1) ? h3 : h2);
            }
            const float* Vr = Vcur + (nw + kb * 8 + c) * VSTR;
#pragma unroll
            for (int nt8 = 0; nt8 < 8; nt8++) {
                unsigned b0 = f2u(Vr[nt8 * 8 + r]);
                unsigned b1 = f2u(Vr[4 * VSTR + nt8 * 8 + r]);
                mma_tf32(of[nt8], a, b0, b1);
            }
        }

        CP_WAIT0();
        __syncthreads();
    }

    // combine warp pairs' O partials (staging reuses Q area)
    float* stg = sh + (warp >> 1) * 1024;   // [16 rows][64 dims]
    if (nwi == 1) {
#pragma unroll
        for (int nt8 = 0; nt8 < 8; nt8++) {
            *(float2*)&stg[r * 64 + nt8 * 8 + 2 * c] =
                make_float2(of[nt8][0], of[nt8][1]);
            *(float2*)&stg[(r + 8) * 64 + nt8 * 8 + 2 * c] =
                make_float2(of[nt8][2], of[nt8][3]);
        }
    }
    __syncthreads();
    if (nwi == 0) {
        float* ab = g_a + ((size_t)(b * SEQ + q0 + mw + r)) * DMODEL + h * DHEAD;
#pragma unroll
        for (int nt8 = 0; nt8 < 8; nt8++) {
            float2 s0 = *(float2*)&stg[r * 64 + nt8 * 8 + 2 * c];
            float2 s1 = *(float2*)&stg[(r + 8) * 64 + nt8 * 8 + 2 * c];
            *(float2*)(ab + nt8 * 8 + 2 * c) =
                make_float2(of[nt8][0] + s0.x, of[nt8][1] + s0.y);
            *(float2*)(ab + (size_t)8 * DMODEL + nt8 * 8 + 2 * c) =
                make_float2(of[nt8][2] + s1.x, of[nt8][3] + s1.y);
        }
    }
}

// ----------------------------------------------------------------------------
extern "C" void kernel_launch(void* const* d_in, const int* in_sizes, int n_in,
                              void* d_out, int out_size)
{
    const float* Q    = (const float*)d_in[0];
    const float* K    = (const float*)d_in[1];
    const float* V    = (const float*)d_in[2];
    const float* mask = (const float*)d_in[3];
    const float* Wq_w = (const float*)d_in[4];
    const float* Wq_b = (const float*)d_in[5];
    const float* Wk_w = (const float*)d_in[6];
    const float* Wk_b = (const float*)d_in[7];
    const float* Wv_w = (const float*)d_in[8];
    const float* Wv_b = (const float*)d_in[9];
    const float* Wo_w = (const float*)d_in[10];
    const float* Wo_b = (const float*)d_in[11];

    float* out = (float*)d_out;
    float* wts = out + (size_t)BATCH * SEQ * DMODEL;

    float *qb, *kb, *vb, *ab;
    cudaGetSymbolAddress((void**)&qb, g_q);
    cudaGetSymbolAddress((void**)&kb, g_k);
    cudaGetSymbolAddress((void**)&vb, g_v);
    cudaGetSymbolAddress((void**)&ab, g_a);

    const int attn_smem = ATTN_SMEM_FLOATS * 4;
    cudaFuncSetAttribute(attn5,
                         cudaFuncAttributeMaxDynamicSharedMemorySize, attn_smem);

    dim3 gg(512 / 64, (BATCH * SEQ) / 128);
    gemm2<2><<<gg, 256>>>(Q, Wq_w, Wq_b, qb);   // tf32-rounded, pre-scaled 1/8
    gemm2<1><<<gg, 256>>>(K, Wk_w, Wk_b, kb);   // tf32-rounded
    gemm2<1><<<gg, 256>>>(V, Wv_w, Wv_b, vb);   // tf32-rounded

    attn5<<<dim3(SEQ / 64, BATCH * NHEAD), 256, attn_smem>>>(mask, wts);

    gemm2<0><<<gg, 256>>>(ab, Wo_w, Wo_b, out); // plain fp32 out
}

// round 7
// speedup vs baseline: 1.1149x; 1.1149x over previous
#include <cuda_runtime.h>
#include <cstdint>

#define BATCH 4
#define SEQ   2048
#define DMODEL 512
#define NHEAD 8
#define DHEAD 64
#define NKT  (SEQ / 64)  // 32 k-tiles

// Scratch (allocation-free rule: __device__ globals)
__device__ float g_q[(size_t)BATCH * SEQ * DMODEL];
__device__ float g_k[(size_t)BATCH * SEQ * DMODEL];
__device__ float g_v[(size_t)BATCH * SEQ * DMODEL];
__device__ float g_a[(size_t)BATCH * SEQ * DMODEL];

__device__ __forceinline__ float to_tf32(float x) {
    asm("cvt.rna.tf32.f32 %0, %0;" : "+f"(x));
    return x;
}
__device__ __forceinline__ unsigned f2u(float x) { return __float_as_uint(x); }
__device__ __forceinline__ unsigned s2u(const void* p) {
    return (unsigned)__cvta_generic_to_shared(p);
}

__device__ __forceinline__ void mma_tf32(float c[4], const unsigned a[4],
                                         unsigned b0, unsigned b1)
{
    asm volatile(
        "mma.sync.aligned.m16n8k8.row.col.f32.tf32.tf32.f32 "
        "{%0,%1,%2,%3}, {%4,%5,%6,%7}, {%8,%9}, {%0,%1,%2,%3};\n"
        : "+f"(c[0]), "+f"(c[1]), "+f"(c[2]), "+f"(c[3])
        : "r"(a[0]), "r"(a[1]), "r"(a[2]), "r"(a[3]), "r"(b0), "r"(b1));
}

__device__ __forceinline__ void ldsm4(unsigned r[4], unsigned addr) {
    asm volatile("ldmatrix.sync.aligned.m8n8.x4.shared.b16 {%0,%1,%2,%3}, [%4];"
        : "=r"(r[0]), "=r"(r[1]), "=r"(r[2]), "=r"(r[3]) : "r"(addr));
}

#define CP16(dst, src) \
    asm volatile("cp.async.cg.shared.global [%0], [%1], 16;" :: "r"(dst), "l"(src))
#define CP_COMMIT()  asm volatile("cp.async.commit_group;")
#define CP_WAIT0()   asm volatile("cp.async.wait_group 0;" ::: "memory")

// ----------------------------------------------------------------------------
// tf32 GEMM + bias body. C[M,512] = A[M,512] @ W[512,512] + b.
// ROUND: round result (×scale) to tf32 before store.
// ----------------------------------------------------------------------------
template<bool ROUND>
__device__ __forceinline__ void gemm_body(
    const float* __restrict__ A, const float* __restrict__ W,
    const float* __restrict__ bias, float* __restrict__ C, float scale)
{
    __shared__ float As[2][128 * 20];
    __shared__ float Wt[2][64 * 20];

    const int tid = threadIdx.x;
    const int lane = tid & 31, warp = tid >> 5;
    const int mw = (warp >> 1) * 32;
    const int nw = (warp & 1) * 32;
    const int r = lane >> 2, c = lane & 3;

    float acc[2][4][4];
#pragma unroll
    for (int i = 0; i < 2; i++)
#pragma unroll
        for (int j = 0; j < 4; j++)
#pragma unroll
            for (int k = 0; k < 4; k++) acc[i][j][k] = 0.f;

    const float* Ab = A + (size_t)blockIdx.y * 128 * 512;
    const float* Wb = W + blockIdx.x * 64;

    const int arow = tid >> 2, ac4 = tid & 3;
    const int wrow = tid >> 4, wc4 = tid & 15;

    unsigned uA0 = s2u(&As[0][0]) +
        (((mw + (lane & 15)) * 20) + ((lane >> 4) << 2)) * 4;
    unsigned uA1 = uA0 + 16 * 20 * 4;
    unsigned uB0 = s2u(&Wt[0][0]) +
        (((nw + (lane & 7) + ((lane >> 4) << 3)) * 20) + (((lane >> 3) & 1) << 2)) * 4;
    unsigned uB1 = uB0 + 16 * 20 * 4;

    float4 aR0, aR1, wR;
    aR0 = *(const float4*)(Ab + (size_t)arow * 512 + ac4 * 4);
    aR1 = *(const float4*)(Ab + (size_t)(arow + 64) * 512 + ac4 * 4);
    wR  = *(const float4*)(Wb + (size_t)wrow * 512 + wc4 * 4);
    {
        float4 v = aR0;
        v.x = to_tf32(v.x); v.y = to_tf32(v.y); v.z = to_tf32(v.z); v.w = to_tf32(v.w);
        *(float4*)&As[0][arow * 20 + ac4 * 4] = v;
        v = aR1;
        v.x = to_tf32(v.x); v.y = to_tf32(v.y); v.z = to_tf32(v.z); v.w = to_tf32(v.w);
        *(float4*)&As[0][(arow + 64) * 20 + ac4 * 4] = v;
        Wt[0][(wc4 * 4 + 0) * 20 + wrow] = to_tf32(wR.x);
        Wt[0][(wc4 * 4 + 1) * 20 + wrow] = to_tf32(wR.y);
        Wt[0][(wc4 * 4 + 2) * 20 + wrow] = to_tf32(wR.z);
        Wt[0][(wc4 * 4 + 3) * 20 + wrow] = to_tf32(wR.w);
    }
    __syncthreads();

    for (int k0 = 0; k0 < 512; k0 += 16) {
        const int cur = (k0 >> 4) & 1;
        const bool nxt = (k0 + 16) < 512;
        if (nxt) {
            aR0 = *(const float4*)(Ab + (size_t)arow * 512 + k0 + 16 + ac4 * 4);
            aR1 = *(const float4*)(Ab + (size_t)(arow + 64) * 512 + k0 + 16 + ac4 * 4);
            wR  = *(const float4*)(Wb + (size_t)(k0 + 16 + wrow) * 512 + wc4 * 4);
        }
#pragma unroll
        for (int ks = 0; ks < 16; ks += 8) {
            unsigned a0[4], a1[4], bF[4];
            ldsm4(a0, uA0 + cur * 10240 + ks * 4);
            ldsm4(a1, uA1 + cur * 10240 + ks * 4);
            ldsm4(bF, uB0 + cur * 5120 + ks * 4);
            mma_tf32(acc[0][0], a0, bF[0], bF[1]);
            mma_tf32(acc[0][1], a0, bF[2], bF[3]);
            mma_tf32(acc[1][0], a1, bF[0], bF[1]);
            mma_tf32(acc[1][1], a1, bF[2], bF[3]);
            ldsm4(bF, uB1 + cur * 5120 + ks * 4);
            mma_tf32(acc[0][2], a0, bF[0], bF[1]);
            mma_tf32(acc[0][3], a0, bF[2], bF[3]);
            mma_tf32(acc[1][2], a1, bF[0], bF[1]);
            mma_tf32(acc[1][3], a1, bF[2], bF[3]);
        }
        if (nxt) {
            const int nb = cur ^ 1;
            float4 v = aR0;
            v.x = to_tf32(v.x); v.y = to_tf32(v.y); v.z = to_tf32(v.z); v.w = to_tf32(v.w);
            *(float4*)&As[nb][arow * 20 + ac4 * 4] = v;
            v = aR1;
            v.x = to_tf32(v.x); v.y = to_tf32(v.y); v.z = to_tf32(v.z); v.w = to_tf32(v.w);
            *(float4*)&As[nb][(arow + 64) * 20 + ac4 * 4] = v;
            Wt[nb][(wc4 * 4 + 0) * 20 + wrow] = to_tf32(wR.x);
            Wt[nb][(wc4 * 4 + 1) * 20 + wrow] = to_tf32(wR.y);
            Wt[nb][(wc4 * 4 + 2) * 20 + wrow] = to_tf32(wR.z);
            Wt[nb][(wc4 * 4 + 3) * 20 + wrow] = to_tf32(wR.w);
        }
        __syncthreads();
    }

#pragma unroll
    for (int mt = 0; mt < 2; mt++)
#pragma unroll
    for (int nt = 0; nt < 4; nt++) {
        int col = blockIdx.x * 64 + nw + nt * 8 + 2 * c;
        float bx = __ldg(bias + col), by = __ldg(bias + col + 1);
        size_t row0 = blockIdx.y * 128 + mw + mt * 16 + r;
        float v0 = acc[mt][nt][0] + bx, v1 = acc[mt][nt][1] + by;
        float v2 = acc[mt][nt][2] + bx, v3 = acc[mt][nt][3] + by;
        if (ROUND) {
            v0 = to_tf32(v0 * scale); v1 = to_tf32(v1 * scale);
            v2 = to_tf32(v2 * scale); v3 = to_tf32(v3 * scale);
        }
        *(float2*)(C + row0 * 512 + col) = make_float2(v0, v1);
        *(float2*)(C + (row0 + 8) * 512 + col) = make_float2(v2, v3);
    }
}

// Fused QKV projections: grid (8, 64, 3)
__global__ void __launch_bounds__(256) gemm_qkv(
    const float* __restrict__ Aq, const float* __restrict__ Ak,
    const float* __restrict__ Av,
    const float* __restrict__ Wq, const float* __restrict__ Wk,
    const float* __restrict__ Wv,
    const float* __restrict__ bq, const float* __restrict__ bk,
    const float* __restrict__ bv,
    float* __restrict__ Cq, float* __restrict__ Ck, float* __restrict__ Cv)
{
    const int z = blockIdx.z;
    const float* A = (z == 0) ? Aq : (z == 1) ? Ak : Av;
    const float* W = (z == 0) ? Wq : (z == 1) ? Wk : Wv;
    const float* bb = (z == 0) ? bq : (z == 1) ? bk : bv;
    float* C = (z == 0) ? Cq : (z == 1) ? Ck : Cv;
    gemm_body<true>(A, W, bb, C, (z == 0) ? 0.125f : 1.f);
}

__global__ void __launch_bounds__(256) gemm_o(
    const float* __restrict__ A, const float* __restrict__ W,
    const float* __restrict__ bias, float* __restrict__ C)
{
    gemm_body<false>(A, W, bias, C, 1.f);
}

// ----------------------------------------------------------------------------
// Flash attention v7 = v6 with correct cp.async wait->barrier ordering.
// Pass B per tile: issue V(kt)+K(kt+1); S from K(kt); weights+P(smem);
// WAIT0 + barrier (V,K visible); PV; barrier (V buffer reuse).
// Smem floats: Q[64*68] K[2*64*68] V[64*72] P[8*16*36] msk[2048] stats[256]
// ----------------------------------------------------------------------------
#define QSTR 68
#define VSTR 72
#define OFF_K   4352
#define OFF_V   13056
#define OFF_P   17664
#define OFF_MSK 22272
#define OFF_ST  24320
#define ATTN_SMEM_FLOATS 24576
#define KBUF_BYTES (4352 * 4)

__global__ void __launch_bounds__(256, 2) attn7(
    const float* __restrict__ mask, float* __restrict__ wts)
{
    extern __shared__ float sh[];
    float* msk = sh + OFF_MSK;
    float* statsf = sh + OFF_ST;   // [row][nwi] partial row-sums

    const int tid = threadIdx.x;
    const int lane = tid & 31, warp = tid >> 5;
    const int mw = (warp >> 1) * 16;
    const int nwi = warp & 1;
    const int nw = nwi * 32;
    const int r = lane >> 2, c = lane & 3;

    const int qt = blockIdx.x, bh = blockIdx.y;
    const int b = bh >> 3, h = bh & 7;
    const int q0 = qt * 64;

    const float* qg = g_q + ((size_t)(b * SEQ + q0)) * DMODEL + h * DHEAD;
    const float* kg = g_k + (size_t)b * SEQ * DMODEL + h * DHEAD;
    const float* vg = g_v + (size_t)b * SEQ * DMODEL + h * DHEAD;
    float* wb = wts + ((size_t)bh * SEQ + q0) * SEQ;

    const unsigned uQst = s2u(sh);
    const unsigned uKst = s2u(sh + OFF_K);
    const unsigned uVst = s2u(sh + OFF_V);

    // prologue: Q + K0
#pragma unroll
    for (int i = 0; i < 4; i++) {
        int f = tid + 256 * i;
        int row = f >> 4, c4 = f & 15;
        CP16(uQst + (unsigned)(row * QSTR + c4 * 4) * 4,
             qg + (size_t)row * DMODEL + c4 * 4);
        CP16(uKst + (unsigned)(row * QSTR + c4 * 4) * 4,
             kg + (size_t)row * DMODEL + c4 * 4);
    }
    CP_COMMIT();
#pragma unroll
    for (int j = 0; j < 2; j++) {
        int idx = tid + 256 * j;
        float4 mv = *(const float4*)(mask + (size_t)b * SEQ + idx * 4);
        msk[idx * 4 + 0] = mv.x * -1e9f;
        msk[idx * 4 + 1] = mv.y * -1e9f;
        msk[idx * 4 + 2] = mv.z * -1e9f;
        msk[idx * 4 + 3] = mv.w * -1e9f;
    }
    CP_WAIT0();
    __syncthreads();

    // fragment base addresses
    const unsigned uQ = uQst +
        (((mw + (lane & 15)) * QSTR) + ((lane >> 4) << 2)) * 4;
    unsigned uK[2];
#pragma unroll
    for (int ntp = 0; ntp < 2; ntp++)
        uK[ntp] = uKst +
            (((nw + ntp * 16 + (lane & 7) + ((lane >> 4) << 3)) * QSTR) +
             (((lane >> 3) & 1) << 2)) * 4;

    float l0 = 0.f, l1 = 0.f;    // register row-sums (rows mw+r, mw+r+8)

    // ======================= Pass A: QK -> sum exp =======================
#pragma unroll 1
    for (int kt = 0; kt < NKT; ++kt) {
        const int cur = kt & 1;
        if (kt + 1 < NKT) {
            const int nb = (kt + 1) & 1;
            const float* src = kg + (size_t)(kt + 1) * 64 * DMODEL;
#pragma unroll
            for (int i = 0; i < 4; i++) {
                int f = tid + 256 * i;
                int row = f >> 4, c4 = f & 15;
                CP16(uKst + nb * KBUF_BYTES + (unsigned)(row * QSTR + c4 * 4) * 4,
                     src + (size_t)row * DMODEL + c4 * 4);
            }
            CP_COMMIT();
        }

        float sf[4][4];
#pragma unroll
        for (int nt = 0; nt < 4; nt++)
#pragma unroll
            for (int j = 0; j < 4; j++) sf[nt][j] = 0.f;

#pragma unroll
        for (int ks = 0; ks < 64; ks += 8) {
            unsigned a[4], bF[4];
            ldsm4(a, uQ + ks * 4);
            ldsm4(bF, uK[0] + cur * KBUF_BYTES + ks * 4);
            mma_tf32(sf[0], a, bF[0], bF[1]);
            mma_tf32(sf[1], a, bF[2], bF[3]);
            ldsm4(bF, uK[1] + cur * KBUF_BYTES + ks * 4);
            mma_tf32(sf[2], a, bF[0], bF[1]);
            mma_tf32(sf[3], a, bF[2], bF[3]);
        }

        float s0 = 0.f, s1 = 0.f;
#pragma unroll
        for (int nt = 0; nt < 4; nt++) {
            int col = nw + nt * 8 + 2 * c;
            float mk0 = msk[kt * 64 + col], mk1 = msk[kt * 64 + col + 1];
            s0 += __expf(sf[nt][0] + mk0) + __expf(sf[nt][1] + mk1);
            s1 += __expf(sf[nt][2] + mk0) + __expf(sf[nt][3] + mk1);
        }
        s0 += __shfl_xor_sync(0xffffffffu, s0, 1);
        s0 += __shfl_xor_sync(0xffffffffu, s0, 2);
        s1 += __shfl_xor_sync(0xffffffffu, s1, 1);
        s1 += __shfl_xor_sync(0xffffffffu, s1, 2);
        l0 += s0;
        l1 += s1;

        CP_WAIT0();        // own copies done...
        __syncthreads();   // ...barrier ⇒ everyone's copies visible next iter
    }

    // combine warp-pair sums (once)
    if (c == 0) {
        statsf[(mw + r) * 2 + nwi] = l0;
        statsf[(mw + r + 8) * 2 + nwi] = l1;
    }

    // pass-B prologue: K0
#pragma unroll
    for (int i = 0; i < 4; i++) {
        int f = tid + 256 * i;
        int row = f >> 4, c4 = f & 15;
        CP16(uKst + (unsigned)(row * QSTR + c4 * 4) * 4,
             kg + (size_t)row * DMODEL + c4 * 4);
    }
    CP_COMMIT();
    CP_WAIT0();          // K0 landed (own)...
    __syncthreads();     // ...and visible to all; statsf also visible

    const float il0 = 1.f / (statsf[(mw + r) * 2] + statsf[(mw + r) * 2 + 1]);
    const float il1 = 1.f / (statsf[(mw + r + 8) * 2] + statsf[(mw + r + 8) * 2 + 1]);

    // ======================= Pass B: weights + PV =======================
    float of[8][4];
#pragma unroll
    for (int nt8 = 0; nt8 < 8; nt8++)
#pragma unroll
        for (int j = 0; j < 4; j++) of[nt8][j] = 0.f;

    float* Pw = sh + OFF_P + warp * 576;             // 16 x 36 warp-private
    const unsigned uPw = s2u(sh + OFF_P) + (unsigned)(warp * 576 * 4) +
                         (unsigned)((lane & 15) * 36 * 4);

#pragma unroll 1
    for (int kt = 0; kt < NKT; ++kt) {
        const int cur = kt & 1;
        const bool haveK = (kt + 1 < NKT);

        // issue V(kt) into single buffer (safe: barrier at end of prev iter)
        {
            const float* vsrc = vg + (size_t)kt * 64 * DMODEL;
#pragma unroll
            for (int i = 0; i < 4; i++) {
                int f = tid + 256 * i;
                int row = f >> 4, c4 = f & 15;
                CP16(uVst + (unsigned)(row * VSTR + c4 * 4) * 4,
                     vsrc + (size_t)row * DMODEL + c4 * 4);
            }
        }
        if (haveK) {
            const int nb = (kt + 1) & 1;
            const float* ksrc = kg + (size_t)(kt + 1) * 64 * DMODEL;
#pragma unroll
            for (int i = 0; i < 4; i++) {
                int f = tid + 256 * i;
                int row = f >> 4, c4 = f & 15;
                CP16(uKst + nb * KBUF_BYTES + (unsigned)(row * QSTR + c4 * 4) * 4,
                     ksrc + (size_t)row * DMODEL + c4 * 4);
            }
        }
        CP_COMMIT();

        // recompute S from K(kt) — resident since previous wait+barrier
        float sf[4][4];
#pragma unroll
        for (int nt = 0; nt < 4; nt++)
#pragma unroll
            for (int j = 0; j < 4; j++) sf[nt][j] = 0.f;
#pragma unroll
        for (int ks = 0; ks < 64; ks += 8) {
            unsigned a[4], bF[4];
            ldsm4(a, uQ + ks * 4);
            ldsm4(bF, uK[0] + cur * KBUF_BYTES + ks * 4);
            mma_tf32(sf[0], a, bF[0], bF[1]);
            mma_tf32(sf[1], a, bF[2], bF[3]);
            ldsm4(bF, uK[1] + cur * KBUF_BYTES + ks * 4);
            mma_tf32(sf[2], a, bF[0], bF[1]);
            mma_tf32(sf[3], a, bF[2], bF[3]);
        }

        // p = exp(s+mk)*il; write weights; store tf32 p to warp-private smem
#pragma unroll
        for (int nt = 0; nt < 4; nt++) {
            int col = nw + nt * 8 + 2 * c;
            float mk0 = msk[kt * 64 + col], mk1 = msk[kt * 64 + col + 1];
            float p0 = __expf(sf[nt][0] + mk0) * il0;
            float p1 = __expf(sf[nt][1] + mk1) * il0;
            float p2 = __expf(sf[nt][2] + mk0) * il1;
            float p3 = __expf(sf[nt][3] + mk1) * il1;
            float* wp = wb + (size_t)(mw + r) * SEQ + kt * 64 + col;
            *(float2*)wp = make_float2(p0, p1);
            *(float2*)(wp + 8 * SEQ) = make_float2(p2, p3);
            // swizzled warp-private store: quad q, key off 2*(c&1)
            int q = 2 * nt + (c >> 1);
            int off = 2 * (c & 1);
            *(float2*)&Pw[r * 36 + (q << 2) + off] =
                make_float2(to_tf32(p0), to_tf32(p1));
            *(float2*)&Pw[(r + 8) * 36 + ((q ^ 4) << 2) + off] =
                make_float2(to_tf32(p2), to_tf32(p3));
        }
        __syncwarp();

        CP_WAIT0();        // V(kt) + K(kt+1): own copies done...
        __syncthreads();   // ...everyone's copies visible

        // PV: A-frags via ldmatrix from warp-private P, scalar V B-frags
        const float* Vs_ = sh + OFF_V;
#pragma unroll
        for (int kb = 0; kb < 4; kb++) {
            unsigned a[4];
            int q0f = kb * 2 + (lane >> 4);
            int qs = q0f ^ ((lane >> 1) & 4);
            ldsm4(a, uPw + (unsigned)(qs << 4));
            const float* Vr = Vs_ + (nw + kb * 8 + c) * VSTR;
#pragma unroll
            for (int nt8 = 0; nt8 < 8; nt8++) {
                unsigned b0 = f2u(Vr[nt8 * 8 + r]);
                unsigned b1 = f2u(Vr[4 * VSTR + nt8 * 8 + r]);
                mma_tf32(of[nt8], a, b0, b1);
            }
        }

        __syncthreads();   // V reads done before next iteration overwrites
    }

    // combine warp pairs' O partials (staging reuses Q area)
    float* stg = sh + (warp >> 1) * 1024;   // [16 rows][64 dims]
    if (nwi == 1) {
#pragma unroll
        for (int nt8 = 0; nt8 < 8; nt8++) {
            *(float2*)&stg[r * 64 + nt8 * 8 + 2 * c] =
                make_float2(of[nt8][0], of[nt8][1]);
            *(float2*)&stg[(r + 8) * 64 + nt8 * 8 + 2 * c] =
                make_float2(of[nt8][2], of[nt8][3]);
        }
    }
    __syncthreads();
    if (nwi == 0) {
        float* ab = g_a + ((size_t)(b * SEQ + q0 + mw + r)) * DMODEL + h * DHEAD;
#pragma unroll
        for (int nt8 = 0; nt8 < 8; nt8++) {
            float2 s0 = *(float2*)&stg[r * 64 + nt8 * 8 + 2 * c];
            float2 s1 = *(float2*)&stg[(r + 8) * 64 + nt8 * 8 + 2 * c];
            *(float2*)(ab + nt8 * 8 + 2 * c) =
                make_float2(of[nt8][0] + s0.x, of[nt8][1] + s0.y);
            *(float2*)(ab + (size_t)8 * DMODEL + nt8 * 8 + 2 * c) =
                make_float2(of[nt8][2] + s1.x, of[nt8][3] + s1.y);
        }
    }
}

// ----------------------------------------------------------------------------
extern "C" void kernel_launch(void* const* d_in, const int* in_sizes, int n_in,
                              void* d_out, int out_size)
{
    const float* Q    = (const float*)d_in[0];
    const float* K    = (const float*)d_in[1];
    const float* V    = (const float*)d_in[2];
    const float* mask = (const float*)d_in[3];
    const float* Wq_w = (const float*)d_in[4];
    const float* Wq_b = (const float*)d_in[5];
    const float* Wk_w = (const float*)d_in[6];
    const float* Wk_b = (const float*)d_in[7];
    const float* Wv_w = (const float*)d_in[8];
    const float* Wv_b = (const float*)d_in[9];
    const float* Wo_w = (const float*)d_in[10];
    const float* Wo_b = (const float*)d_in[11];

    float* out = (float*)d_out;
    float* wts = out + (size_t)BATCH * SEQ * DMODEL;

    float *qb, *kb, *vb, *ab;
    cudaGetSymbolAddress((void**)&qb, g_q);
    cudaGetSymbolAddress((void**)&kb, g_k);
    cudaGetSymbolAddress((void**)&vb, g_v);
    cudaGetSymbolAddress((void**)&ab, g_a);

    const int attn_smem = ATTN_SMEM_FLOATS * 4;
    cudaFuncSetAttribute(attn7,
                         cudaFuncAttributeMaxDynamicSharedMemorySize, attn_smem);

    dim3 gqkv(512 / 64, (BATCH * SEQ) / 128, 3);
    gemm_qkv<<<gqkv, 256>>>(Q, K, V, Wq_w, Wk_w, Wv_w,
                            Wq_b, Wk_b, Wv_b, qb, kb, vb);

    attn7<<<dim3(SEQ / 64, BATCH * NHEAD), 256, attn_smem>>>(mask, wts);

    dim3 gg(512 / 64, (BATCH * SEQ) / 128);
    gemm_o<<<gg, 256>>>(ab, Wo_w, Wo_b, out);
}

// round 8
// speedup vs baseline: 1.2717x; 1.1407x over previous
#include <cuda_runtime.h>
#include <cstdint>

#define BATCH 4
#define SEQ   2048
#define DMODEL 512
#define NHEAD 8
#define DHEAD 64
#define NKT  (SEQ / 64)  // 32 k-tiles

// Scratch (allocation-free rule: __device__ globals)
__device__ float g_q[(size_t)BATCH * SEQ * DMODEL];
__device__ float g_k[(size_t)BATCH * SEQ * DMODEL];
__device__ float g_v[(size_t)BATCH * SEQ * DMODEL];
__device__ float g_a[(size_t)BATCH * SEQ * DMODEL];
__device__ float g_wt[(size_t)4 * DMODEL * DMODEL];   // transposed tf32 weights

__device__ __forceinline__ float to_tf32(float x) {
    asm("cvt.rna.tf32.f32 %0, %0;" : "+f"(x));
    return x;
}
__device__ __forceinline__ unsigned f2u(float x) { return __float_as_uint(x); }
__device__ __forceinline__ unsigned s2u(const void* p) {
    return (unsigned)__cvta_generic_to_shared(p);
}

__device__ __forceinline__ void mma_tf32(float c[4], const unsigned a[4],
                                         unsigned b0, unsigned b1)
{
    asm volatile(
        "mma.sync.aligned.m16n8k8.row.col.f32.tf32.tf32.f32 "
        "{%0,%1,%2,%3}, {%4,%5,%6,%7}, {%8,%9}, {%0,%1,%2,%3};\n"
        : "+f"(c[0]), "+f"(c[1]), "+f"(c[2]), "+f"(c[3])
        : "r"(a[0]), "r"(a[1]), "r"(a[2]), "r"(a[3]), "r"(b0), "r"(b1));
}

__device__ __forceinline__ void ldsm4(unsigned r[4], unsigned addr) {
    asm volatile("ldmatrix.sync.aligned.m8n8.x4.shared.b16 {%0,%1,%2,%3}, [%4];"
        : "=r"(r[0]), "=r"(r[1]), "=r"(r[2]), "=r"(r[3]) : "r"(addr));
}

#define CP16(dst, src) \
    asm volatile("cp.async.cg.shared.global [%0], [%1], 16;" :: "r"(dst), "l"(src))
#define CP_COMMIT()  asm volatile("cp.async.commit_group;")
#define CP_WAIT0()   asm volatile("cp.async.wait_group 0;" ::: "memory")
#define CP_WAIT1()   asm volatile("cp.async.wait_group 1;" ::: "memory")

// ----------------------------------------------------------------------------
// prep_w: transpose + tf32-round weights.  out[n][k] = tf32(W[k][n])
// grid (16,16,4), block (32,8)
// ----------------------------------------------------------------------------
__global__ void prep_w(const float* __restrict__ W0, const float* __restrict__ W1,
                       const float* __restrict__ W2, const float* __restrict__ W3,
                       float* __restrict__ O)
{
    __shared__ float t[32][33];
    const float* W = (blockIdx.z == 0) ? W0 : (blockIdx.z == 1) ? W1
                   : (blockIdx.z == 2) ? W2 : W3;
    float* out = O + (size_t)blockIdx.z * DMODEL * DMODEL;
    const int bx = blockIdx.x * 32, by = blockIdx.y * 32;
    const int tx = threadIdx.x, ty = threadIdx.y;
#pragma unroll
    for (int i = 0; i < 32; i += 8)
        t[ty + i][tx] = W[(size_t)(by + ty + i) * DMODEL + bx + tx];
    __syncthreads();
#pragma unroll
    for (int i = 0; i < 32; i += 8)
        out[(size_t)(bx + ty + i) * DMODEL + by + tx] = to_tf32(t[tx][ty + i]);
}

// ----------------------------------------------------------------------------
// gemm3: tf32 GEMM + bias with pre-transposed W^T [n][k].
// BM=128, BN=64, BK=16, 3-stage cp.async pipeline, 1 barrier/tile.
// 8 warps (4m x 2n), warp tile 32x32. A-frags tf32-rounded post-ldmatrix.
// ROUND: round (×scale) outputs to tf32.
// ----------------------------------------------------------------------------
template<bool ROUND>
__device__ __forceinline__ void gemm3_body(
    const float* __restrict__ A, const float* __restrict__ Wt,
    const float* __restrict__ bias, float* __restrict__ C, float scale)
{
    __shared__ float As[3][128 * 20];
    __shared__ float Ws[3][64 * 20];

    const int tid = threadIdx.x;
    const int lane = tid & 31, warp = tid >> 5;
    const int mw = (warp >> 1) * 32;
    const int nw = (warp & 1) * 32;
    const int r = lane >> 2, c = lane & 3;

    float acc[2][4][4];
#pragma unroll
    for (int i = 0; i < 2; i++)
#pragma unroll
        for (int j = 0; j < 4; j++)
#pragma unroll
            for (int k = 0; k < 4; k++) acc[i][j][k] = 0.f;

    const float* Ab = A + (size_t)blockIdx.y * 128 * 512;
    const float* Wb = Wt + (size_t)blockIdx.x * 64 * 512;

    const unsigned uA = s2u(&As[0][0]);
    const unsigned uW = s2u(&Ws[0][0]);

    auto issue = [&](int k0, int s) {
#pragma unroll
        for (int i = 0; i < 2; i++) {
            int f = tid + 256 * i;
            int row = f >> 2, c4 = f & 3;
            CP16(uA + (unsigned)(s * 10240) + (unsigned)(row * 20 + c4 * 4) * 4,
                 Ab + (size_t)row * 512 + k0 + c4 * 4);
        }
        {
            int row = tid >> 2, c4 = tid & 3;
            CP16(uW + (unsigned)(s * 5120) + (unsigned)(row * 20 + c4 * 4) * 4,
                 Wb + (size_t)row * 512 + k0 + c4 * 4);
        }
    };

    const unsigned fA = ((mw + (lane & 15)) * 20 + ((lane >> 4) << 2)) * 4;
    const unsigned fB = ((nw + (lane & 7) + ((lane >> 4) << 3)) * 20 +
                        (((lane >> 3) & 1) << 2)) * 4;

    issue(0, 0);  CP_COMMIT();
    issue(16, 1); CP_COMMIT();
    CP_WAIT1();
    __syncthreads();

#pragma unroll 1
    for (int t = 0; t < 32; ++t) {
        const int s = t % 3;
        const unsigned aBase = uA + (unsigned)(s * 10240) + fA;
        const unsigned bBase = uW + (unsigned)(s * 5120) + fB;
#pragma unroll
        for (int ks = 0; ks < 16; ks += 8) {
            unsigned a0[4], a1[4], bF[4];
            ldsm4(a0, aBase + ks * 4);
            ldsm4(a1, aBase + 16 * 20 * 4 + ks * 4);
#pragma unroll
            for (int j = 0; j < 4; j++) {
                a0[j] = f2u(to_tf32(__uint_as_float(a0[j])));
                a1[j] = f2u(to_tf32(__uint_as_float(a1[j])));
            }
            ldsm4(bF, bBase + ks * 4);
            mma_tf32(acc[0][0], a0, bF[0], bF[1]);
            mma_tf32(acc[0][1], a0, bF[2], bF[3]);
            mma_tf32(acc[1][0], a1, bF[0], bF[1]);
            mma_tf32(acc[1][1], a1, bF[2], bF[3]);
            ldsm4(bF, bBase + 16 * 20 * 4 + ks * 4);
            mma_tf32(acc[0][2], a0, bF[0], bF[1]);
            mma_tf32(acc[0][3], a0, bF[2], bF[3]);
            mma_tf32(acc[1][2], a1, bF[0], bF[1]);
            mma_tf32(acc[1][3], a1, bF[2], bF[3]);
        }
        if (t + 2 < 32) issue((t + 2) * 16, (t + 2) % 3);
        CP_COMMIT();
        CP_WAIT1();
        __syncthreads();
    }

#pragma unroll
    for (int mt = 0; mt < 2; mt++)
#pragma unroll
    for (int nt = 0; nt < 4; nt++) {
        int col = blockIdx.x * 64 + nw + nt * 8 + 2 * c;
        float bx = __ldg(bias + col), by = __ldg(bias + col + 1);
        size_t row0 = blockIdx.y * 128 + mw + mt * 16 + r;
        float v0 = acc[mt][nt][0] + bx, v1 = acc[mt][nt][1] + by;
        float v2 = acc[mt][nt][2] + bx, v3 = acc[mt][nt][3] + by;
        if (ROUND) {
            v0 = to_tf32(v0 * scale); v1 = to_tf32(v1 * scale);
            v2 = to_tf32(v2 * scale); v3 = to_tf32(v3 * scale);
        }
        *(float2*)(C + row0 * 512 + col) = make_float2(v0, v1);
        *(float2*)(C + (row0 + 8) * 512 + col) = make_float2(v2, v3);
    }
}

// Fused QKV projections: grid (8, 64, 3); W^T from g_wt slots 0..2
__global__ void __launch_bounds__(256, 3) gemm_qkv3(
    const float* __restrict__ Aq, const float* __restrict__ Ak,
    const float* __restrict__ Av, const float* __restrict__ Wt,
    const float* __restrict__ bq, const float* __restrict__ bk,
    const float* __restrict__ bv,
    float* __restrict__ Cq, float* __restrict__ Ck, float* __restrict__ Cv)
{
    const int z = blockIdx.z;
    const float* A = (z == 0) ? Aq : (z == 1) ? Ak : Av;
    const float* W = Wt + (size_t)z * DMODEL * DMODEL;
    const float* bb = (z == 0) ? bq : (z == 1) ? bk : bv;
    float* C = (z == 0) ? Cq : (z == 1) ? Ck : Cv;
    gemm3_body<true>(A, W, bb, C, (z == 0) ? 0.125f : 1.f);
}

__global__ void __launch_bounds__(256, 3) gemm_o3(
    const float* __restrict__ A, const float* __restrict__ Wt,
    const float* __restrict__ bias, float* __restrict__ C)
{
    gemm3_body<false>(A, Wt, bias, C, 1.f);
}

// ----------------------------------------------------------------------------
// Flash attention v7 (unchanged from round 7 — passing, race-free).
// ----------------------------------------------------------------------------
#define QSTR 68
#define VSTR 72
#define OFF_K   4352
#define OFF_V   13056
#define OFF_P   17664
#define OFF_MSK 22272
#define OFF_ST  24320
#define ATTN_SMEM_FLOATS 24576
#define KBUF_BYTES (4352 * 4)

__global__ void __launch_bounds__(256, 2) attn7(
    const float* __restrict__ mask, float* __restrict__ wts)
{
    extern __shared__ float sh[];
    float* msk = sh + OFF_MSK;
    float* statsf = sh + OFF_ST;

    const int tid = threadIdx.x;
    const int lane = tid & 31, warp = tid >> 5;
    const int mw = (warp >> 1) * 16;
    const int nwi = warp & 1;
    const int nw = nwi * 32;
    const int r = lane >> 2, c = lane & 3;

    const int qt = blockIdx.x, bh = blockIdx.y;
    const int b = bh >> 3, h = bh & 7;
    const int q0 = qt * 64;

    const float* qg = g_q + ((size_t)(b * SEQ + q0)) * DMODEL + h * DHEAD;
    const float* kg = g_k + (size_t)b * SEQ * DMODEL + h * DHEAD;
    const float* vg = g_v + (size_t)b * SEQ * DMODEL + h * DHEAD;
    float* wb = wts + ((size_t)bh * SEQ + q0) * SEQ;

    const unsigned uQst = s2u(sh);
    const unsigned uKst = s2u(sh + OFF_K);
    const unsigned uVst = s2u(sh + OFF_V);

#pragma unroll
    for (int i = 0; i < 4; i++) {
        int f = tid + 256 * i;
        int row = f >> 4, c4 = f & 15;
        CP16(uQst + (unsigned)(row * QSTR + c4 * 4) * 4,
             qg + (size_t)row * DMODEL + c4 * 4);
        CP16(uKst + (unsigned)(row * QSTR + c4 * 4) * 4,
             kg + (size_t)row * DMODEL + c4 * 4);
    }
    CP_COMMIT();
#pragma unroll
    for (int j = 0; j < 2; j++) {
        int idx = tid + 256 * j;
        float4 mv = *(const float4*)(mask + (size_t)b * SEQ + idx * 4);
        msk[idx * 4 + 0] = mv.x * -1e9f;
        msk[idx * 4 + 1] = mv.y * -1e9f;
        msk[idx * 4 + 2] = mv.z * -1e9f;
        msk[idx * 4 + 3] = mv.w * -1e9f;
    }
    CP_WAIT0();
    __syncthreads();

    const unsigned uQ = uQst +
        (((mw + (lane & 15)) * QSTR) + ((lane >> 4) << 2)) * 4;
    unsigned uK[2];
#pragma unroll
    for (int ntp = 0; ntp < 2; ntp++)
        uK[ntp] = uKst +
            (((nw + ntp * 16 + (lane & 7) + ((lane >> 4) << 3)) * QSTR) +
             (((lane >> 3) & 1) << 2)) * 4;

    float l0 = 0.f, l1 = 0.f;

    // ======================= Pass A: QK -> sum exp =======================
#pragma unroll 1
    for (int kt = 0; kt < NKT; ++kt) {
        const int cur = kt & 1;
        if (kt + 1 < NKT) {
            const int nb = (kt + 1) & 1;
            const float* src = kg + (size_t)(kt + 1) * 64 * DMODEL;
#pragma unroll
            for (int i = 0; i < 4; i++) {
                int f = tid + 256 * i;
                int row = f >> 4, c4 = f & 15;
                CP16(uKst + nb * KBUF_BYTES + (unsigned)(row * QSTR + c4 * 4) * 4,
                     src + (size_t)row * DMODEL + c4 * 4);
            }
            CP_COMMIT();
        }

        float sf[4][4];
#pragma unroll
        for (int nt = 0; nt < 4; nt++)
#pragma unroll
            for (int j = 0; j < 4; j++) sf[nt][j] = 0.f;

#pragma unroll
        for (int ks = 0; ks < 64; ks += 8) {
            unsigned a[4], bF[4];
            ldsm4(a, uQ + ks * 4);
            ldsm4(bF, uK[0] + cur * KBUF_BYTES + ks * 4);
            mma_tf32(sf[0], a, bF[0], bF[1]);
            mma_tf32(sf[1], a, bF[2], bF[3]);
            ldsm4(bF, uK[1] + cur * KBUF_BYTES + ks * 4);
            mma_tf32(sf[2], a, bF[0], bF[1]);
            mma_tf32(sf[3], a, bF[2], bF[3]);
        }

        float s0 = 0.f, s1 = 0.f;
#pragma unroll
        for (int nt = 0; nt < 4; nt++) {
            int col = nw + nt * 8 + 2 * c;
            float mk0 = msk[kt * 64 + col], mk1 = msk[kt * 64 + col + 1];
            s0 += __expf(sf[nt][0] + mk0) + __expf(sf[nt][1] + mk1);
            s1 += __expf(sf[nt][2] + mk0) + __expf(sf[nt][3] + mk1);
        }
        s0 += __shfl_xor_sync(0xffffffffu, s0, 1);
        s0 += __shfl_xor_sync(0xffffffffu, s0, 2);
        s1 += __shfl_xor_sync(0xffffffffu, s1, 1);
        s1 += __shfl_xor_sync(0xffffffffu, s1, 2);
        l0 += s0;
        l1 += s1;

        CP_WAIT0();
        __syncthreads();
    }

    if (c == 0) {
        statsf[(mw + r) * 2 + nwi] = l0;
        statsf[(mw + r + 8) * 2 + nwi] = l1;
    }

    // pass-B prologue: K0
#pragma unroll
    for (int i = 0; i < 4; i++) {
        int f = tid + 256 * i;
        int row = f >> 4, c4 = f & 15;
        CP16(uKst + (unsigned)(row * QSTR + c4 * 4) * 4,
             kg + (size_t)row * DMODEL + c4 * 4);
    }
    CP_COMMIT();
    CP_WAIT0();
    __syncthreads();

    const float il0 = 1.f / (statsf[(mw + r) * 2] + statsf[(mw + r) * 2 + 1]);
    const float il1 = 1.f / (statsf[(mw + r + 8) * 2] + statsf[(mw + r + 8) * 2 + 1]);

    // ======================= Pass B: weights + PV =======================
    float of[8][4];
#pragma unroll
    for (int nt8 = 0; nt8 < 8; nt8++)
#pragma unroll
        for (int j = 0; j < 4; j++) of[nt8][j] = 0.f;

    float* Pw = sh + OFF_P + warp * 576;
    const unsigned uPw = s2u(sh + OFF_P) + (unsigned)(warp * 576 * 4) +
                         (unsigned)((lane & 15) * 36 * 4);

#pragma unroll 1
    for (int kt = 0; kt < NKT; ++kt) {
        const int cur = kt & 1;
        const bool haveK = (kt + 1 < NKT);

        {
            const float* vsrc = vg + (size_t)kt * 64 * DMODEL;
#pragma unroll
            for (int i = 0; i < 4; i++) {
                int f = tid + 256 * i;
                int row = f >> 4, c4 = f & 15;
                CP16(uVst + (unsigned)(row * VSTR + c4 * 4) * 4,
                     vsrc + (size_t)row * DMODEL + c4 * 4);
            }
        }
        if (haveK) {
            const int nb = (kt + 1) & 1;
            const float* ksrc = kg + (size_t)(kt + 1) * 64 * DMODEL;
#pragma unroll
            for (int i = 0; i < 4; i++) {
                int f = tid + 256 * i;
                int row = f >> 4, c4 = f & 15;
                CP16(uKst + nb * KBUF_BYTES + (unsigned)(row * QSTR + c4 * 4) * 4,
                     ksrc + (size_t)row * DMODEL + c4 * 4);
            }
        }
        CP_COMMIT();

        float sf[4][4];
#pragma unroll
        for (int nt = 0; nt < 4; nt++)
#pragma unroll
            for (int j = 0; j < 4; j++) sf[nt][j] = 0.f;
#pragma unroll
        for (int ks = 0; ks < 64; ks += 8) {
            unsigned a[4], bF[4];
            ldsm4(a, uQ + ks * 4);
            ldsm4(bF, uK[0] + cur * KBUF_BYTES + ks * 4);
            mma_tf32(sf[0], a, bF[0], bF[1]);
            mma_tf32(sf[1], a, bF[2], bF[3]);
            ldsm4(bF, uK[1] + cur * KBUF_BYTES + ks * 4);
            mma_tf32(sf[2], a, bF[0], bF[1]);
            mma_tf32(sf[3], a, bF[2], bF[3]);
        }

#pragma unroll
        for (int nt = 0; nt < 4; nt++) {
            int col = nw + nt * 8 + 2 * c;
            float mk0 = msk[kt * 64 + col], mk1 = msk[kt * 64 + col + 1];
            float p0 = __expf(sf[nt][0] + mk0) * il0;
            float p1 = __expf(sf[nt][1] + mk1) * il0;
            float p2 = __expf(sf[nt][2] + mk0) * il1;
            float p3 = __expf(sf[nt][3] + mk1) * il1;
            float* wp = wb + (size_t)(mw + r) * SEQ + kt * 64 + col;
            *(float2*)wp = make_float2(p0, p1);
            *(float2*)(wp + 8 * SEQ) = make_float2(p2, p3);
            int q = 2 * nt + (c >> 1);
            int off = 2 * (c & 1);
            *(float2*)&Pw[r * 36 + (q << 2) + off] =
                make_float2(to_tf32(p0), to_tf32(p1));
            *(float2*)&Pw[(r + 8) * 36 + ((q ^ 4) << 2) + off] =
                make_float2(to_tf32(p2), to_tf32(p3));
        }
        __syncwarp();

        CP_WAIT0();
        __syncthreads();

        const float* Vs_ = sh + OFF_V;
#pragma unroll
        for (int kb = 0; kb < 4; kb++) {
            unsigned a[4];
            int q0f = kb * 2 + (lane >> 4);
            int qs = q0f ^ ((lane >> 1) & 4);
            ldsm4(a, uPw + (unsigned)(qs << 4));
            const float* Vr = Vs_ + (nw + kb * 8 + c) * VSTR;
#pragma unroll
            for (int nt8 = 0; nt8 < 8; nt8++) {
                unsigned b0 = f2u(Vr[nt8 * 8 + r]);
                unsigned b1 = f2u(Vr[4 * VSTR + nt8 * 8 + r]);
                mma_tf32(of[nt8], a, b0, b1);
            }
        }

        __syncthreads();
    }

    float* stg = sh + (warp >> 1) * 1024;
    if (nwi == 1) {
#pragma unroll
        for (int nt8 = 0; nt8 < 8; nt8++) {
            *(float2*)&stg[r * 64 + nt8 * 8 + 2 * c] =
                make_float2(of[nt8][0], of[nt8][1]);
            *(float2*)&stg[(r + 8) * 64 + nt8 * 8 + 2 * c] =
                make_float2(of[nt8][2], of[nt8][3]);
        }
    }
    __syncthreads();
    if (nwi == 0) {
        float* ab = g_a + ((size_t)(b * SEQ + q0 + mw + r)) * DMODEL + h * DHEAD;
#pragma unroll
        for (int nt8 = 0; nt8 < 8; nt8++) {
            float2 s0 = *(float2*)&stg[r * 64 + nt8 * 8 + 2 * c];
            float2 s1 = *(float2*)&stg[(r + 8) * 64 + nt8 * 8 + 2 * c];
            *(float2*)(ab + nt8 * 8 + 2 * c) =
                make_float2(of[nt8][0] + s0.x, of[nt8][1] + s0.y);
            *(float2*)(ab + (size_t)8 * DMODEL + nt8 * 8 + 2 * c) =
                make_float2(of[nt8][2] + s1.x, of[nt8][3] + s1.y);
        }
    }
}

// ----------------------------------------------------------------------------
extern "C" void kernel_launch(void* const* d_in, const int* in_sizes, int n_in,
                              void* d_out, int out_size)
{
    const float* Q    = (const float*)d_in[0];
    const float* K    = (const float*)d_in[1];
    const float* V    = (const float*)d_in[2];
    const float* mask = (const float*)d_in[3];
    const float* Wq_w = (const float*)d_in[4];
    const float* Wq_b = (const float*)d_in[5];
    const float* Wk_w = (const float*)d_in[6];
    const float* Wk_b = (const float*)d_in[7];
    const float* Wv_w = (const float*)d_in[8];
    const float* Wv_b = (const float*)d_in[9];
    const float* Wo_w = (const float*)d_in[10];
    const float* Wo_b = (const float*)d_in[11];

    float* out = (float*)d_out;
    float* wts = out + (size_t)BATCH * SEQ * DMODEL;

    float *qb, *kb, *vb, *ab, *wt;
    cudaGetSymbolAddress((void**)&qb, g_q);
    cudaGetSymbolAddress((void**)&kb, g_k);
    cudaGetSymbolAddress((void**)&vb, g_v);
    cudaGetSymbolAddress((void**)&ab, g_a);
    cudaGetSymbolAddress((void**)&wt, g_wt);

    const int attn_smem = ATTN_SMEM_FLOATS * 4;
    cudaFuncSetAttribute(attn7,
                         cudaFuncAttributeMaxDynamicSharedMemorySize, attn_smem);

    prep_w<<<dim3(16, 16, 4), dim3(32, 8)>>>(Wq_w, Wk_w, Wv_w, Wo_w, wt);

    dim3 gqkv(512 / 64, (BATCH * SEQ) / 128, 3);
    gemm_qkv3<<<gqkv, 256>>>(Q, K, V, wt, Wq_b, Wk_b, Wv_b, qb, kb, vb);

    attn7<<<dim3(SEQ / 64, BATCH * NHEAD), 256, attn_smem>>>(mask, wts);

    dim3 gg(512 / 64, (BATCH * SEQ) / 128);
    gemm_o3<<<gg, 256>>>(ab, wt + (size_t)3 * DMODEL * DMODEL, Wo_b, out);
}